// round 6
// baseline (speedup 1.0000x reference)
#include <cuda_runtime.h>
#include <cuda_bf16.h>
#include <cstdint>
#include <math.h>

// ============================================================================
// ScaledDotAttention via mma.sync (HMMA bf16), sm_103-compatible PTX only.
//   out = softmax((Q.Mem^T/sqrt(D)) * W) . Mem     Q=4096, M=8192, D=128 fp32
//
// Round 5 changes vs R4 (178.7 us, tensor=49%, L1=53%, issue=23%):
//  - pass-major MMA ordering in BOTH GEMMs: same-accumulator reuse distance
//    1 -> 4 (breaks HMMA accumulation dependency chains so tensor and shared
//    pipes overlap instead of serializing)
//  - PV B fragments loaded in groups of 4 nf before their 12 MMAs
// ============================================================================

namespace {
constexpr int QT = 4096, MT = 8192, DD = 128;
constexpr int BQ = 32, BM = 128, TILES = MT / BM;   // 64 tiles
constexpr int THREADS = 256;

// smem layout (bytes)
constexpr int S_QH   = 0;                 // Q hi  [2 d-halves][32 rows][64 bf16] = 8KB
constexpr int S_QL   = 8192;              // Q lo  = 8KB
constexpr int S_M    = 16384;             // Mem stages: 2 x (hi 32KB + lo 32KB)
constexpr int STAGE  = 65536;
constexpr int S_MH_OFF = 0;
constexpr int S_ML_OFF = 32768;
constexpr int S_LSUM = S_M + 2 * STAGE;   // 147456
constexpr int SMEM_TOTAL = S_LSUM + 512;
}

// preprocessed bf16 hi/lo operands
__device__ __align__(16) __nv_bfloat16 g_q_h[QT * DD];
__device__ __align__(16) __nv_bfloat16 g_q_l[QT * DD];
__device__ __align__(16) __nv_bfloat16 g_m_h[MT * DD];
__device__ __align__(16) __nv_bfloat16 g_m_l[MT * DD];

// ---------------- helpers ----------------
__device__ __forceinline__ uint32_t smem_to_u32(const void* p) {
    uint32_t a;
    asm("{ .reg .u64 t; cvta.to.shared.u64 t, %1; cvt.u32.u64 %0, t; }" : "=r"(a) : "l"(p));
    return a;
}
__device__ __forceinline__ uint32_t sw128(uint32_t o) { return o ^ ((o >> 3) & 0x70); }

__device__ __forceinline__ void ldsm_x4(uint32_t* r, uint32_t a) {
    asm volatile("ldmatrix.sync.aligned.m8n8.x4.shared.b16 {%0,%1,%2,%3}, [%4];"
                 : "=r"(r[0]), "=r"(r[1]), "=r"(r[2]), "=r"(r[3]) : "r"(a));
}
__device__ __forceinline__ void ldsm_x4t(uint32_t* r, uint32_t a) {
    asm volatile("ldmatrix.sync.aligned.m8n8.x4.trans.shared.b16 {%0,%1,%2,%3}, [%4];"
                 : "=r"(r[0]), "=r"(r[1]), "=r"(r[2]), "=r"(r[3]) : "r"(a));
}
__device__ __forceinline__ void mma_bf16(float* c, const uint32_t* a, const uint32_t* b) {
    asm volatile("mma.sync.aligned.m16n8k16.row.col.f32.bf16.bf16.f32 "
                 "{%0,%1,%2,%3}, {%4,%5,%6,%7}, {%8,%9}, {%0,%1,%2,%3};"
                 : "+f"(c[0]), "+f"(c[1]), "+f"(c[2]), "+f"(c[3])
                 : "r"(a[0]), "r"(a[1]), "r"(a[2]), "r"(a[3]), "r"(b[0]), "r"(b[1]));
}
__device__ __forceinline__ uint32_t pack_bf16x2(float lo, float hi) {
    __nv_bfloat162 v = __floats2bfloat162_rn(lo, hi);
    return *reinterpret_cast<uint32_t*>(&v);
}
#define CP_ASYNC16(dst, src) \
    asm volatile("cp.async.cg.shared.global [%0], [%1], 16;" :: "r"(dst), "l"(src))
#define CP_COMMIT() asm volatile("cp.async.commit_group;" ::: "memory")
#define CP_WAIT1()  asm volatile("cp.async.wait_group 1;" ::: "memory")

// ---------------- merged prep kernel ----------------
__global__ void prep_kernel(const float* __restrict__ q, const float* __restrict__ m) {
    int idx = blockIdx.x * blockDim.x + threadIdx.x;
    if (idx < QT * DD) {
        float v = q[idx] * 0.088388347648318440550f;   // 1/sqrt(128)
        __nv_bfloat16 h = __float2bfloat16(v);
        g_q_h[idx] = h;
        g_q_l[idx] = __float2bfloat16(v - __bfloat162float(h));
    }
    int midx = idx - QT * DD;
    if (midx >= 0 && midx < MT * DD) {
        float v = m[midx];
        __nv_bfloat16 h = __float2bfloat16(v);
        g_m_h[midx] = h;
        g_m_l[midx] = __float2bfloat16(v - __bfloat162float(h));
    }
}

// ---------------- main kernel ----------------
__global__ __launch_bounds__(THREADS, 1)
void attn_mma_kernel(const float* __restrict__ weights, float* __restrict__ out)
{
    extern __shared__ char smem[];
    const uint32_t sb = smem_to_u32(smem);
    const int tid  = threadIdx.x;
    const int wid  = tid >> 5;
    const int lane = tid & 31;
    const int mw   = wid & 1;
    const int kw   = wid >> 1;
    const int gid  = lane >> 2;
    const int tig  = lane & 3;
    const int q0   = blockIdx.x * BQ;
    const int qrow0 = mw * 16;
    const int j0w   = kw * 32;

    float* lsum = (float*)(smem + S_LSUM);
    if (tid < 32) lsum[tid] = 0.f;

    // ---- load Q tile hi/lo ----
    for (int it = tid; it < 32 * 16; it += THREADS) {
        int row = it >> 4, ch = it & 15;
        uint32_t o = sw128((uint32_t)((ch >> 3) * 4096 + row * 128 + (ch & 7) * 16));
        *(uint4*)(smem + S_QH + o) = *(const uint4*)(g_q_h + (size_t)(q0 + row) * DD + ch * 8);
        *(uint4*)(smem + S_QL + o) = *(const uint4*)(g_q_l + (size_t)(q0 + row) * DD + ch * 8);
    }

    // per-lane addressing
    const int rowA   = qrow0 + (lane & 15);
    const int selA   = lane >> 4;
    const int sb_row = ((lane >> 4) & 1) * 8 + (lane & 7);
    const int sb_sel = (lane >> 3) & 1;
    const int pv_row = lane & 15;
    const int pv_sel = lane >> 4;

    float o_acc[16][4];
    #pragma unroll
    for (int i = 0; i < 16; ++i)
        #pragma unroll
        for (int e = 0; e < 4; ++e) o_acc[i][e] = 0.f;
    float rs0 = 0.f, rs1 = 0.f;

    const float* wbase = weights + (size_t)(q0 + qrow0 + gid) * MT + j0w + tig * 2;

    auto load_tile = [&](int t, int buf) {
        const int m0 = t * BM;
        const uint32_t base = sb + S_M + buf * STAGE;
        for (int it = tid; it < BM * 16; it += THREADS) {
            int row = it >> 4, ch = it & 15;
            uint32_t o = sw128((uint32_t)((ch >> 3) * 16384 + row * 128 + (ch & 7) * 16));
            size_t gs = (size_t)(m0 + row) * DD + ch * 8;
            CP_ASYNC16(base + S_MH_OFF + o, (const void*)(g_m_h + gs));
            CP_ASYNC16(base + S_ML_OFF + o, (const void*)(g_m_l + gs));
        }
    };

    load_tile(0, 0);
    CP_COMMIT();

    for (int t = 0; t < TILES; ++t) {
        if (t + 1 < TILES) load_tile(t + 1, (t + 1) & 1);
        CP_COMMIT();
        CP_WAIT1();
        __syncthreads();

        const uint32_t mbase = sb + S_M + (t & 1) * STAGE;
        const uint32_t mh = mbase + S_MH_OFF;
        const uint32_t ml = mbase + S_ML_OFF;

        // ---- weights prefetch ----
        float wreg[4][4];
        {
            const float* wp = wbase + (size_t)t * BM;
            #pragma unroll
            for (int nf = 0; nf < 4; ++nf) {
                float2 w0 = *(const float2*)(wp + nf * 8);
                float2 w1 = *(const float2*)(wp + nf * 8 + (size_t)8 * MT);
                wreg[nf][0] = w0.x; wreg[nf][1] = w0.y;
                wreg[nf][2] = w1.x; wreg[nf][3] = w1.y;
            }
        }

        // ---- S = Q . Mem^T (16x32 per warp), pass-major MMA ordering ----
        float sf[4][4];
        #pragma unroll
        for (int nf = 0; nf < 4; ++nf)
            #pragma unroll
            for (int e = 0; e < 4; ++e) sf[nf][e] = 0.f;

        #pragma unroll
        for (int k = 0; k < 8; ++k) {
            const int half = k >> 2;
            const int cb   = (k & 3) * 2;
            uint32_t ao = sw128((uint32_t)(half * 4096 + rowA * 128 + (cb + selA) * 16));
            uint32_t Ah[4], Al[4];
            ldsm_x4(Ah, sb + S_QH + ao);
            ldsm_x4(Al, sb + S_QL + ao);

            uint32_t Bh[8], Bl[8];
            #pragma unroll
            for (int nfb = 0; nfb < 4; nfb += 2) {
                uint32_t bo = sw128((uint32_t)(half * 16384
                                    + (j0w + nfb * 8 + sb_row) * 128
                                    + (cb + sb_sel) * 16));
                ldsm_x4(Bh + nfb * 2, mh + bo);
                ldsm_x4(Bl + nfb * 2, ml + bo);
            }
            // pass 1: Ah . Bh   (acc reuse distance 4)
            #pragma unroll
            for (int nf = 0; nf < 4; ++nf) mma_bf16(sf[nf], Ah, Bh + nf * 2);
            // pass 2: Al . Bh
            #pragma unroll
            for (int nf = 0; nf < 4; ++nf) mma_bf16(sf[nf], Al, Bh + nf * 2);
            // pass 3: Ah . Bl
            #pragma unroll
            for (int nf = 0; nf < 4; ++nf) mma_bf16(sf[nf], Ah, Bl + nf * 2);
        }

        // ---- weights * S, exp, split P into bf16 hi/lo A-fragments ----
        uint32_t aPh[2][4], aPl[2][4];
        #pragma unroll
        for (int nf = 0; nf < 4; ++nf) {
            float p[4];
            #pragma unroll
            for (int e = 0; e < 4; ++e) p[e] = __expf(sf[nf][e] * wreg[nf][e]);
            rs0 += p[0] + p[1];
            rs1 += p[2] + p[3];

            uint32_t h01 = pack_bf16x2(p[0], p[1]);
            uint32_t h23 = pack_bf16x2(p[2], p[3]);
            __nv_bfloat162 hv01 = *reinterpret_cast<__nv_bfloat162*>(&h01);
            __nv_bfloat162 hv23 = *reinterpret_cast<__nv_bfloat162*>(&h23);
            float l0 = p[0] - __bfloat162float(hv01.x);
            float l1 = p[1] - __bfloat162float(hv01.y);
            float l2 = p[2] - __bfloat162float(hv23.x);
            float l3 = p[3] - __bfloat162float(hv23.y);

            const int kf = nf >> 1;
            const int hi = (nf & 1) * 2;
            aPh[kf][hi]     = h01;
            aPh[kf][hi + 1] = h23;
            aPl[kf][hi]     = pack_bf16x2(l0, l1);
            aPl[kf][hi + 1] = pack_bf16x2(l2, l3);
        }

        // ---- O += P . Mem, groups of 4 nf, pass-major ordering ----
        #pragma unroll
        for (int kf = 0; kf < 2; ++kf) {
            const int jb = (j0w + kf * 16 + pv_row) * 128;
            #pragma unroll
            for (int nfg = 0; nfg < 16; nfg += 4) {
                uint32_t Bh[8], Bl[8];
                #pragma unroll
                for (int nfb = 0; nfb < 4; nfb += 2) {
                    const int nf = nfg + nfb;
                    uint32_t bo = sw128((uint32_t)((nf >> 3) * 16384 + jb
                                        + ((nf & 7) + pv_sel) * 16));
                    ldsm_x4t(Bh + nfb * 2, mh + bo);
                    ldsm_x4t(Bl + nfb * 2, ml + bo);
                }
                // pass 1: Ph . Mh   (acc reuse distance 4)
                #pragma unroll
                for (int nfb = 0; nfb < 4; ++nfb)
                    mma_bf16(o_acc[nfg + nfb], aPh[kf], Bh + nfb * 2);
                // pass 2: Pl . Mh
                #pragma unroll
                for (int nfb = 0; nfb < 4; ++nfb)
                    mma_bf16(o_acc[nfg + nfb], aPl[kf], Bh + nfb * 2);
                // pass 3: Ph . Ml
                #pragma unroll
                for (int nfb = 0; nfb < 4; ++nfb)
                    mma_bf16(o_acc[nfg + nfb], aPh[kf], Bl + nfb * 2);
            }
        }
        __syncthreads();
    }

    // ---- row-sum reduction ----
    rs0 += __shfl_xor_sync(0xffffffffu, rs0, 1);
    rs0 += __shfl_xor_sync(0xffffffffu, rs0, 2);
    rs1 += __shfl_xor_sync(0xffffffffu, rs1, 1);
    rs1 += __shfl_xor_sync(0xffffffffu, rs1, 2);
    if (tig == 0) {
        atomicAdd(&lsum[qrow0 + gid], rs0);
        atomicAdd(&lsum[qrow0 + gid + 8], rs1);
    }
    __syncthreads();

    // ---- O reduction across kw warps via smem ----
    float* sO = (float*)(smem + S_QH);   // [32][128]
    for (int i = tid; i < 32 * 128; i += THREADS) sO[i] = 0.f;
    __syncthreads();
    #pragma unroll
    for (int nf = 0; nf < 16; ++nf) {
        const int cbase = nf * 8 + tig * 2;
        atomicAdd(&sO[(qrow0 + gid) * 128 + cbase],         o_acc[nf][0]);
        atomicAdd(&sO[(qrow0 + gid) * 128 + cbase + 1],     o_acc[nf][1]);
        atomicAdd(&sO[(qrow0 + gid + 8) * 128 + cbase],     o_acc[nf][2]);
        atomicAdd(&sO[(qrow0 + gid + 8) * 128 + cbase + 1], o_acc[nf][3]);
    }
    __syncthreads();

    // ---- normalize + store ----
    for (int i = tid; i < 32 * 32; i += THREADS) {
        int r  = i >> 5;
        int c4 = (i & 31) * 4;
        float inv = 1.0f / lsum[r];
        float4 v = *(float4*)(&sO[r * 128 + c4]);
        v.x *= inv; v.y *= inv; v.z *= inv; v.w *= inv;
        *(float4*)(&out[(size_t)(q0 + r) * DD + c4]) = v;
    }
}

// ---------------- launch ----------------
extern "C" void kernel_launch(void* const* d_in, const int* in_sizes, int n_in,
                              void* d_out, int out_size)
{
    const float* query   = (const float*)d_in[0];
    const float* memory  = (const float*)d_in[1];
    const float* weights = (const float*)d_in[2];
    float* out = (float*)d_out;

    cudaFuncSetAttribute(attn_mma_kernel,
                         cudaFuncAttributeMaxDynamicSharedMemorySize, SMEM_TOTAL);

    prep_kernel<<<((QT + MT) * DD + 255) / 256, 256>>>(query, memory);
    attn_mma_kernel<<<QT / BQ, THREADS, SMEM_TOTAL>>>(weights, out);
}

// round 7
// speedup vs baseline: 1.1427x; 1.1427x over previous
#include <cuda_runtime.h>
#include <cuda_bf16.h>
#include <cstdint>
#include <math.h>

// ============================================================================
// ScaledDotAttention via mma.sync (HMMA bf16), sm_103-compatible PTX only.
//   out = softmax((Q.Mem^T/sqrt(D)) * W) . Mem     Q=4096, M=8192, D=128 fp32
//
// Round 6 changes vs R4/R5 (178.7 us, tensor=49%, L1=53%, issue=23%):
//  - DESYNCHRONIZED warp pairs: each kw pair owns its private 32-row Mem
//    quarter (2-stage cp.async) and syncs only via a 64-thread named barrier.
//    The 4 pairs drift out of phase, so ldsm bursts of one pair overlap the
//    HMMA bursts of another -> shared and tensor pipes overlap instead of
//    alternating (they summed to ~100% serialized before).
// ============================================================================

namespace {
constexpr int QT = 4096, MT = 8192, DD = 128;
constexpr int BQ = 32, BM = 128, TILES = MT / BM;   // 64 tiles
constexpr int THREADS = 256;

// smem layout (bytes)
constexpr int S_QH  = 0;          // Q hi  [2 d-halves][32 rows][64 bf16] = 8KB
constexpr int S_QL  = 8192;       // Q lo  = 8KB
constexpr int S_M   = 16384;      // 4 pairs x 2 stages x 16KB quarter = 128KB
constexpr int QTR   = 16384;      // quarter stage: hi 8KB + lo 8KB
constexpr int S_LSUM = S_M + 8 * QTR;   // 147456
constexpr int SMEM_TOTAL = S_LSUM + 512;
}

// preprocessed bf16 hi/lo operands
__device__ __align__(16) __nv_bfloat16 g_q_h[QT * DD];
__device__ __align__(16) __nv_bfloat16 g_q_l[QT * DD];
__device__ __align__(16) __nv_bfloat16 g_m_h[MT * DD];
__device__ __align__(16) __nv_bfloat16 g_m_l[MT * DD];

// ---------------- helpers ----------------
__device__ __forceinline__ uint32_t smem_to_u32(const void* p) {
    uint32_t a;
    asm("{ .reg .u64 t; cvta.to.shared.u64 t, %1; cvt.u32.u64 %0, t; }" : "=r"(a) : "l"(p));
    return a;
}
__device__ __forceinline__ uint32_t sw128(uint32_t o) { return o ^ ((o >> 3) & 0x70); }

__device__ __forceinline__ void ldsm_x4(uint32_t* r, uint32_t a) {
    asm volatile("ldmatrix.sync.aligned.m8n8.x4.shared.b16 {%0,%1,%2,%3}, [%4];"
                 : "=r"(r[0]), "=r"(r[1]), "=r"(r[2]), "=r"(r[3]) : "r"(a));
}
__device__ __forceinline__ void ldsm_x4t(uint32_t* r, uint32_t a) {
    asm volatile("ldmatrix.sync.aligned.m8n8.x4.trans.shared.b16 {%0,%1,%2,%3}, [%4];"
                 : "=r"(r[0]), "=r"(r[1]), "=r"(r[2]), "=r"(r[3]) : "r"(a));
}
__device__ __forceinline__ void mma_bf16(float* c, const uint32_t* a, const uint32_t* b) {
    asm volatile("mma.sync.aligned.m16n8k16.row.col.f32.bf16.bf16.f32 "
                 "{%0,%1,%2,%3}, {%4,%5,%6,%7}, {%8,%9}, {%0,%1,%2,%3};"
                 : "+f"(c[0]), "+f"(c[1]), "+f"(c[2]), "+f"(c[3])
                 : "r"(a[0]), "r"(a[1]), "r"(a[2]), "r"(a[3]), "r"(b[0]), "r"(b[1]));
}
__device__ __forceinline__ uint32_t pack_bf16x2(float lo, float hi) {
    __nv_bfloat162 v = __floats2bfloat162_rn(lo, hi);
    return *reinterpret_cast<uint32_t*>(&v);
}
#define CP_ASYNC16(dst, src) \
    asm volatile("cp.async.cg.shared.global [%0], [%1], 16;" :: "r"(dst), "l"(src))
#define CP_COMMIT() asm volatile("cp.async.commit_group;" ::: "memory")
#define CP_WAIT1()  asm volatile("cp.async.wait_group 1;" ::: "memory")
#define BAR_PAIR(id) asm volatile("bar.sync %0, 64;" :: "r"(id) : "memory")

// ---------------- merged prep kernel ----------------
__global__ void prep_kernel(const float* __restrict__ q, const float* __restrict__ m) {
    int idx = blockIdx.x * blockDim.x + threadIdx.x;
    if (idx < QT * DD) {
        float v = q[idx] * 0.088388347648318440550f;   // 1/sqrt(128)
        __nv_bfloat16 h = __float2bfloat16(v);
        g_q_h[idx] = h;
        g_q_l[idx] = __float2bfloat16(v - __bfloat162float(h));
    }
    int midx = idx - QT * DD;
    if (midx >= 0 && midx < MT * DD) {
        float v = m[midx];
        __nv_bfloat16 h = __float2bfloat16(v);
        g_m_h[midx] = h;
        g_m_l[midx] = __float2bfloat16(v - __bfloat162float(h));
    }
}

// ---------------- main kernel ----------------
__global__ __launch_bounds__(THREADS, 1)
void attn_mma_kernel(const float* __restrict__ weights, float* __restrict__ out)
{
    extern __shared__ char smem[];
    const uint32_t sb = smem_to_u32(smem);
    const int tid  = threadIdx.x;
    const int wid  = tid >> 5;
    const int lane = tid & 31;
    const int mw   = wid & 1;         // q-row group inside pair
    const int pw   = wid >> 1;        // pair id == j-quarter id (0..3)
    const int gid  = lane >> 2;
    const int tig  = lane & 3;
    const int q0   = blockIdx.x * BQ;
    const int qrow0 = mw * 16;
    const int j0w   = pw * 32;        // pair's 32 Mem rows within the 128-row tile
    const int barid = 1 + pw;

    float* lsum = (float*)(smem + S_LSUM);
    if (tid < 32) lsum[tid] = 0.f;

    // ---- load Q tile hi/lo ----
    for (int it = tid; it < 32 * 16; it += THREADS) {
        int row = it >> 4, ch = it & 15;
        uint32_t o = sw128((uint32_t)((ch >> 3) * 4096 + row * 128 + (ch & 7) * 16));
        *(uint4*)(smem + S_QH + o) = *(const uint4*)(g_q_h + (size_t)(q0 + row) * DD + ch * 8);
        *(uint4*)(smem + S_QL + o) = *(const uint4*)(g_q_l + (size_t)(q0 + row) * DD + ch * 8);
    }

    // per-lane addressing (quarter-local rows)
    const int rowA   = qrow0 + (lane & 15);
    const int selA   = lane >> 4;
    const int sb_row = ((lane >> 4) & 1) * 8 + (lane & 7);
    const int sb_sel = (lane >> 3) & 1;
    const int pv_row = lane & 15;
    const int pv_sel = lane >> 4;

    float o_acc[16][4];
    #pragma unroll
    for (int i = 0; i < 16; ++i)
        #pragma unroll
        for (int e = 0; e < 4; ++e) o_acc[i][e] = 0.f;
    float rs0 = 0.f, rs1 = 0.f;

    const float* wbase = weights + (size_t)(q0 + qrow0 + gid) * MT + j0w + tig * 2;

    // pair's 64 threads load the pair's 32-row quarter (hi+lo), swizzled
    const uint32_t pair_base = sb + S_M + pw * 2 * QTR;
    auto load_quarter = [&](int t, int buf) {
        const int m0 = t * BM + j0w;
        const uint32_t qb = pair_base + buf * QTR;
        int it = tid & 63;
        #pragma unroll
        for (int rep = 0; rep < 8; ++rep, it += 64) {
            int row = it >> 4, ch = it & 15;
            uint32_t o = sw128((uint32_t)((ch >> 3) * 4096 + row * 128 + (ch & 7) * 16));
            size_t gs = (size_t)(m0 + row) * DD + ch * 8;
            CP_ASYNC16(qb + o,        (const void*)(g_m_h + gs));
            CP_ASYNC16(qb + 8192 + o, (const void*)(g_m_l + gs));
        }
    };

    __syncthreads();   // Q tile + lsum ready (also orders before any pair barriers)

    load_quarter(0, 0);
    CP_COMMIT();

    for (int t = 0; t < TILES; ++t) {
        if (t + 1 < TILES) load_quarter(t + 1, (t + 1) & 1);
        CP_COMMIT();
        CP_WAIT1();
        BAR_PAIR(barid);   // all 64 pair threads' tile-t data visible

        const uint32_t mh = pair_base + (t & 1) * QTR;
        const uint32_t ml = mh + 8192;

        // ---- weights prefetch (gmem, hidden under S mma) ----
        float wreg[4][4];
        {
            const float* wp = wbase + (size_t)t * BM;
            #pragma unroll
            for (int nf = 0; nf < 4; ++nf) {
                float2 w0 = *(const float2*)(wp + nf * 8);
                float2 w1 = *(const float2*)(wp + nf * 8 + (size_t)8 * MT);
                wreg[nf][0] = w0.x; wreg[nf][1] = w0.y;
                wreg[nf][2] = w1.x; wreg[nf][3] = w1.y;
            }
        }

        // ---- S = Q . Mem^T (16x32 per warp), pass-major ----
        float sf[4][4];
        #pragma unroll
        for (int nf = 0; nf < 4; ++nf)
            #pragma unroll
            for (int e = 0; e < 4; ++e) sf[nf][e] = 0.f;

        #pragma unroll
        for (int k = 0; k < 8; ++k) {
            const int half = k >> 2;
            const int cb   = (k & 3) * 2;
            uint32_t ao = sw128((uint32_t)(half * 4096 + rowA * 128 + (cb + selA) * 16));
            uint32_t Ah[4], Al[4];
            ldsm_x4(Ah, sb + S_QH + ao);
            ldsm_x4(Al, sb + S_QL + ao);

            uint32_t Bh[8], Bl[8];
            #pragma unroll
            for (int nfb = 0; nfb < 4; nfb += 2) {
                uint32_t bo = sw128((uint32_t)(half * 4096
                                    + (nfb * 8 + sb_row) * 128
                                    + (cb + sb_sel) * 16));
                ldsm_x4(Bh + nfb * 2, mh + bo);
                ldsm_x4(Bl + nfb * 2, ml + bo);
            }
            #pragma unroll
            for (int nf = 0; nf < 4; ++nf) mma_bf16(sf[nf], Ah, Bh + nf * 2);
            #pragma unroll
            for (int nf = 0; nf < 4; ++nf) mma_bf16(sf[nf], Al, Bh + nf * 2);
            #pragma unroll
            for (int nf = 0; nf < 4; ++nf) mma_bf16(sf[nf], Ah, Bl + nf * 2);
        }

        // ---- weights * S, exp, split P into bf16 hi/lo A-fragments ----
        uint32_t aPh[2][4], aPl[2][4];
        #pragma unroll
        for (int nf = 0; nf < 4; ++nf) {
            float p[4];
            #pragma unroll
            for (int e = 0; e < 4; ++e) p[e] = __expf(sf[nf][e] * wreg[nf][e]);
            rs0 += p[0] + p[1];
            rs1 += p[2] + p[3];

            uint32_t h01 = pack_bf16x2(p[0], p[1]);
            uint32_t h23 = pack_bf16x2(p[2], p[3]);
            __nv_bfloat162 hv01 = *reinterpret_cast<__nv_bfloat162*>(&h01);
            __nv_bfloat162 hv23 = *reinterpret_cast<__nv_bfloat162*>(&h23);
            float l0 = p[0] - __bfloat162float(hv01.x);
            float l1 = p[1] - __bfloat162float(hv01.y);
            float l2 = p[2] - __bfloat162float(hv23.x);
            float l3 = p[3] - __bfloat162float(hv23.y);

            const int kf = nf >> 1;
            const int hi = (nf & 1) * 2;
            aPh[kf][hi]     = h01;
            aPh[kf][hi + 1] = h23;
            aPl[kf][hi]     = pack_bf16x2(l0, l1);
            aPl[kf][hi + 1] = pack_bf16x2(l2, l3);
        }

        // ---- O += P . Mem (pair's quarter as K), groups of 4 nf, pass-major ----
        #pragma unroll
        for (int kf = 0; kf < 2; ++kf) {
            const int jb = (kf * 16 + pv_row) * 128;
            #pragma unroll
            for (int nfg = 0; nfg < 16; nfg += 4) {
                uint32_t Bh[8], Bl[8];
                #pragma unroll
                for (int nfb = 0; nfb < 4; nfb += 2) {
                    const int nf = nfg + nfb;
                    uint32_t bo = sw128((uint32_t)((nf >> 3) * 4096 + jb
                                        + ((nf & 7) + pv_sel) * 16));
                    ldsm_x4t(Bh + nfb * 2, mh + bo);
                    ldsm_x4t(Bl + nfb * 2, ml + bo);
                }
                #pragma unroll
                for (int nfb = 0; nfb < 4; ++nfb)
                    mma_bf16(o_acc[nfg + nfb], aPh[kf], Bh + nfb * 2);
                #pragma unroll
                for (int nfb = 0; nfb < 4; ++nfb)
                    mma_bf16(o_acc[nfg + nfb], aPl[kf], Bh + nfb * 2);
                #pragma unroll
                for (int nfb = 0; nfb < 4; ++nfb)
                    mma_bf16(o_acc[nfg + nfb], aPh[kf], Bl + nfb * 2);
            }
        }
        BAR_PAIR(barid);   // pair done reading this stage buffer
    }

    // ---- row-sum reduction ----
    rs0 += __shfl_xor_sync(0xffffffffu, rs0, 1);
    rs0 += __shfl_xor_sync(0xffffffffu, rs0, 2);
    rs1 += __shfl_xor_sync(0xffffffffu, rs1, 1);
    rs1 += __shfl_xor_sync(0xffffffffu, rs1, 2);
    if (tig == 0) {
        atomicAdd(&lsum[qrow0 + gid], rs0);
        atomicAdd(&lsum[qrow0 + gid + 8], rs1);
    }
    __syncthreads();   // reconverge all pairs

    // ---- O reduction across pairs via smem (reuse Q region) ----
    float* sO = (float*)(smem + S_QH);   // [32][128]
    for (int i = tid; i < 32 * 128; i += THREADS) sO[i] = 0.f;
    __syncthreads();
    #pragma unroll
    for (int nf = 0; nf < 16; ++nf) {
        const int cbase = nf * 8 + tig * 2;
        atomicAdd(&sO[(qrow0 + gid) * 128 + cbase],         o_acc[nf][0]);
        atomicAdd(&sO[(qrow0 + gid) * 128 + cbase + 1],     o_acc[nf][1]);
        atomicAdd(&sO[(qrow0 + gid + 8) * 128 + cbase],     o_acc[nf][2]);
        atomicAdd(&sO[(qrow0 + gid + 8) * 128 + cbase + 1], o_acc[nf][3]);
    }
    __syncthreads();

    // ---- normalize + store ----
    for (int i = tid; i < 32 * 32; i += THREADS) {
        int r  = i >> 5;
        int c4 = (i & 31) * 4;
        float inv = 1.0f / lsum[r];
        float4 v = *(float4*)(&sO[r * 128 + c4]);
        v.x *= inv; v.y *= inv; v.z *= inv; v.w *= inv;
        *(float4*)(&out[(size_t)(q0 + r) * DD + c4]) = v;
    }
}

// ---------------- launch ----------------
extern "C" void kernel_launch(void* const* d_in, const int* in_sizes, int n_in,
                              void* d_out, int out_size)
{
    const float* query   = (const float*)d_in[0];
    const float* memory  = (const float*)d_in[1];
    const float* weights = (const float*)d_in[2];
    float* out = (float*)d_out;

    cudaFuncSetAttribute(attn_mma_kernel,
                         cudaFuncAttributeMaxDynamicSharedMemorySize, SMEM_TOTAL);

    prep_kernel<<<((QT + MT) * DD + 255) / 256, 256>>>(query, memory);
    attn_mma_kernel<<<QT / BQ, THREADS, SMEM_TOTAL>>>(weights, out);
}